// round 7
// baseline (speedup 1.0000x reference)
#include <cuda_runtime.h>
#include <cuda_bf16.h>
#include <cstdint>

#define N_NODES 50000
#define N_EDGES 800000
#define D 96
#define NF4 (D/4)   // 24 float4 per row
#define GR 64       // rows per GEMM block

// -------- scratch (static device globals; no allocation allowed) --------
__device__ __align__(16) float g_xw [N_NODES * D];   // X @ W (current layer)
__device__ __align__(16) float g_h  [N_NODES * D];   // layer-1 output
__device__ float g_dinv[N_NODES];                    // 1/sqrt(deg)
__device__ int   g_cnt [N_NODES];                    // in-degree histogram
__device__ int   g_rowptr[N_NODES + 1];              // CSR row pointers (by dst)
__device__ int   g_rowcur[N_NODES];                  // fill cursors (=rowptr copy)
__device__ int   g_csr [N_EDGES];                    // CSR column indices (src)

#define FMA_F32X2(d, a, b, c) \
    asm("fma.rn.f32x2 %0, %1, %2, %3;" : "=l"(d) : "l"(a), "l"(b), "l"(c))
#define PACK_F32X2(out, lo, hi) \
    asm("mov.b64 %0, {%1, %2};" : "=l"(out) : "f"(lo), "f"(hi))
#define UNPACK_F32X2(lo, hi, in) \
    asm("mov.b64 {%0, %1}, %2;" : "=f"(lo), "=f"(hi) : "l"(in))

// ---------------- CSR build ----------------
__global__ void k_count(const int* __restrict__ dst) {
    int e = blockIdx.x * blockDim.x + threadIdx.x;
    if (e < N_EDGES) atomicAdd(&g_cnt[dst[e]], 1);
}

// single-CTA exclusive prefix scan over 50k bins (hierarchical);
// writes rowptr, fill cursors, and dinv
__global__ void __launch_bounds__(1024) k_scan() {
    __shared__ int wsum[32];
    const int T = 1024;
    const int CHUNK = (N_NODES + T - 1) / T;   // 49
    int t = threadIdx.x;
    int lane = t & 31, wid = t >> 5;
    int beg = t * CHUNK;
    int end = min(beg + CHUNK, N_NODES);
    if (beg > N_NODES) beg = N_NODES;
    if (end < beg) end = beg;

    int local = 0;
    for (int i = beg; i < end; i++) local += g_cnt[i];

    int v = local;
    #pragma unroll
    for (int off = 1; off < 32; off <<= 1) {
        int n = __shfl_up_sync(0xFFFFFFFFu, v, off);
        if (lane >= off) v += n;
    }
    if (lane == 31) wsum[wid] = v;
    __syncthreads();
    if (wid == 0) {
        int wv = wsum[lane];
        #pragma unroll
        for (int off = 1; off < 32; off <<= 1) {
            int n = __shfl_up_sync(0xFFFFFFFFu, wv, off);
            if (lane >= off) wv += n;
        }
        wsum[lane] = wv;
    }
    __syncthreads();

    int excl = v - local + (wid > 0 ? wsum[wid - 1] : 0);
    if (t == T - 1) g_rowptr[N_NODES] = excl + local;   // == N_EDGES

    int acc = excl;
    for (int i = beg; i < end; i++) {
        g_rowptr[i] = acc;
        g_rowcur[i] = acc;
        int c = g_cnt[i];
        acc += c;
        g_dinv[i] = rsqrtf(1.0f + (float)c);
    }
}

__global__ void k_fill(const int* __restrict__ src,
                       const int* __restrict__ dst) {
    int e = blockIdx.x * blockDim.x + threadIdx.x;
    if (e >= N_EDGES) return;
    int d = dst[e];
    int pos = atomicAdd(&g_rowcur[d], 1);
    g_csr[pos] = src[e];
}

// ---------------- GEMM: g_xw[N,96] = X[N,96] @ W[96,96] ----------------
// 64 rows / block, 256 threads, packed f32x2 accumulation (FFMA2).
__global__ void __launch_bounds__(256)
k_gemm(const float* __restrict__ Xext, const float* __restrict__ W, int use_h) {
    __shared__ float  Ws[D * D];                 // 36864 B
    __shared__ float2 Xp[D * (GR / 2)];          // 24576 B
    const float* __restrict__ X = use_h ? (const float*)g_h : Xext;

    int t = threadIdx.x;
    int rowBase = blockIdx.x * GR;

    for (int i = t; i < D * D; i += 256) Ws[i] = W[i];

    float* xpf = reinterpret_cast<float*>(Xp);
    for (int i = t; i < GR * (D / 4); i += 256) {
        int r  = i / (D / 4);
        int c4 = i % (D / 4);
        int row = rowBase + r;
        float4 v = (row < N_NODES)
            ? reinterpret_cast<const float4*>(X + (size_t)row * D)[c4]
            : make_float4(0.f, 0.f, 0.f, 0.f);
        int pair = r >> 1, half = r & 1;
        int k0 = c4 * 4;
        xpf[(k0 + 0) * GR + pair * 2 + half] = v.x;
        xpf[(k0 + 1) * GR + pair * 2 + half] = v.y;
        xpf[(k0 + 2) * GR + pair * 2 + half] = v.z;
        xpf[(k0 + 3) * GR + pair * 2 + half] = v.w;
    }
    __syncthreads();

    int ty = t >> 5, tx = t & 31;
    unsigned long long acc[4][3];
    #pragma unroll
    for (int p = 0; p < 4; p++)
        #pragma unroll
        for (int c = 0; c < 3; c++) acc[p][c] = 0ull;

    const unsigned long long* xp64 =
        reinterpret_cast<const unsigned long long*>(Xp);

    #pragma unroll 2
    for (int k = 0; k < D; k++) {
        float w0 = Ws[k * D + tx * 3 + 0];
        float w1 = Ws[k * D + tx * 3 + 1];
        float w2 = Ws[k * D + tx * 3 + 2];
        unsigned long long w0p, w1p, w2p;
        PACK_F32X2(w0p, w0, w0);
        PACK_F32X2(w1p, w1, w1);
        PACK_F32X2(w2p, w2, w2);
        #pragma unroll
        for (int p = 0; p < 4; p++) {
            unsigned long long xv = xp64[k * (GR / 2) + ty * 4 + p];
            FMA_F32X2(acc[p][0], xv, w0p, acc[p][0]);
            FMA_F32X2(acc[p][1], xv, w1p, acc[p][1]);
            FMA_F32X2(acc[p][2], xv, w2p, acc[p][2]);
        }
    }

    #pragma unroll
    for (int p = 0; p < 4; p++) {
        int row0 = rowBase + (ty * 4 + p) * 2;
        #pragma unroll
        for (int c = 0; c < 3; c++) {
            float lo, hi;
            UNPACK_F32X2(lo, hi, acc[p][c]);
            if (row0 < N_NODES)     g_xw[(size_t)row0 * D + tx * 3 + c] = lo;
            if (row0 + 1 < N_NODES) g_xw[(size_t)(row0 + 1) * D + tx * 3 + c] = hi;
        }
    }
}

// ---------------- fused aggregate + bias + relu ----------------
// One warp per node. Warp-cooperative prefetch: lane l loads csr[base+l]
// (one coalesced LDG covers 32 edges) and dinv in parallel; shfl broadcasts
// (s,w) per edge so every row gather is INDEPENDENT (no csr->xw chain).
__global__ void __launch_bounds__(128)
k_agg(const float* __restrict__ b, float* __restrict__ outExt, int to_h) {
    int node = blockIdx.x * 4 + (threadIdx.x >> 5);
    int lane = threadIdx.x & 31;
    if (node >= N_NODES) return;
    bool act = lane < NF4;

    const float4* __restrict__ xw4 = reinterpret_cast<const float4*>(g_xw);
    float di = g_dinv[node];

    float4 a = make_float4(0.f, 0.f, 0.f, 0.f);
    if (act) {
        float4 v = xw4[(size_t)node * NF4 + lane];
        a.x = v.x * di; a.y = v.y * di; a.z = v.z * di; a.w = v.w * di;
    }

    int beg = g_rowptr[node];
    int end = g_rowptr[node + 1];

    for (int base = beg; base < end; base += 32) {
        int n = end - base;
        if (n > 32) n = 32;
        int   sl = (lane < n) ? g_csr[base + lane] : 0;   // 1 coalesced LDG
        float wl = (lane < n) ? g_dinv[sl] : 0.0f;        // parallel gather

        int k = 0;
        for (; k + 4 <= n; k += 4) {
            int   s0 = __shfl_sync(0xFFFFFFFFu, sl, k + 0);
            int   s1 = __shfl_sync(0xFFFFFFFFu, sl, k + 1);
            int   s2 = __shfl_sync(0xFFFFFFFFu, sl, k + 2);
            int   s3 = __shfl_sync(0xFFFFFFFFu, sl, k + 3);
            float w0 = __shfl_sync(0xFFFFFFFFu, wl, k + 0);
            float w1 = __shfl_sync(0xFFFFFFFFu, wl, k + 1);
            float w2 = __shfl_sync(0xFFFFFFFFu, wl, k + 2);
            float w3 = __shfl_sync(0xFFFFFFFFu, wl, k + 3);
            if (act) {
                float4 v0 = xw4[(size_t)s0 * NF4 + lane];
                float4 v1 = xw4[(size_t)s1 * NF4 + lane];
                float4 v2 = xw4[(size_t)s2 * NF4 + lane];
                float4 v3 = xw4[(size_t)s3 * NF4 + lane];
                a.x += v0.x * w0; a.y += v0.y * w0; a.z += v0.z * w0; a.w += v0.w * w0;
                a.x += v1.x * w1; a.y += v1.y * w1; a.z += v1.z * w1; a.w += v1.w * w1;
                a.x += v2.x * w2; a.y += v2.y * w2; a.z += v2.z * w2; a.w += v2.w * w2;
                a.x += v3.x * w3; a.y += v3.y * w3; a.z += v3.z * w3; a.w += v3.w * w3;
            }
        }
        for (; k < n; k++) {
            int   sk = __shfl_sync(0xFFFFFFFFu, sl, k);
            float wk = __shfl_sync(0xFFFFFFFFu, wl, k);
            if (act) {
                float4 v = xw4[(size_t)sk * NF4 + lane];
                a.x += v.x * wk; a.y += v.y * wk; a.z += v.z * wk; a.w += v.w * wk;
            }
        }
    }

    if (act) {
        const float4* __restrict__ b4 = reinterpret_cast<const float4*>(b);
        float4 bb = b4[lane];
        float4 r;
        r.x = fmaxf(a.x * di + bb.x, 0.0f);
        r.y = fmaxf(a.y * di + bb.y, 0.0f);
        r.z = fmaxf(a.z * di + bb.z, 0.0f);
        r.w = fmaxf(a.w * di + bb.w, 0.0f);
        float4* __restrict__ op =
            reinterpret_cast<float4*>(to_h ? g_h : outExt);
        op[(size_t)node * NF4 + lane] = r;
    }
}

// ---------------- launch ----------------
extern "C" void kernel_launch(void* const* d_in, const int* in_sizes, int n_in,
                              void* d_out, int out_size) {
    const float* x   = (const float*)d_in[0];
    const int*   ei  = (const int*)d_in[1];   // [2, E] int32 (JAX x64 disabled)
    const float* W1  = (const float*)d_in[2];
    const float* b1  = (const float*)d_in[3];
    const float* W2  = (const float*)d_in[4];
    const float* b2  = (const float*)d_in[5];
    float*       out = (float*)d_out;

    const int* src = ei;
    const int* dst = ei + N_EDGES;

    // zero the histogram via memset node (no kernel launch)
    void* cntPtr = nullptr;
    cudaGetSymbolAddress(&cntPtr, g_cnt);
    cudaMemsetAsync(cntPtr, 0, N_NODES * sizeof(int));

    const int T = 256;
    int gE    = (N_EDGES + T - 1) / T;
    int gGemm = (N_NODES + GR - 1) / GR;
    int gAgg  = (N_NODES + 3) / 4;            // 4 nodes (warps) per 128-thr CTA

    // CSR build + norms (shared by both layers)
    k_count <<<gE, T>>>(dst);
    k_scan  <<<1, 1024>>>();
    k_fill  <<<gE, T>>>(src, dst);

    // layer 1: h = relu(agg(x @ W1) + b1)
    k_gemm <<<gGemm, T>>>(x, W1, 0);
    k_agg  <<<gAgg, 128>>>(b1, out, 1);

    // layer 2: out = relu(agg(h @ W2) + b2)
    k_gemm <<<gGemm, T>>>(nullptr, W2, 1);
    k_agg  <<<gAgg, 128>>>(b2, out, 0);
}

// round 8
// speedup vs baseline: 1.2856x; 1.2856x over previous
#include <cuda_runtime.h>
#include <cuda_bf16.h>
#include <cstdint>

#define N_NODES 50000
#define N_EDGES 800000
#define D 96
#define KS 12              // k-steps  (96/8)
#define NT 12              // n-tiles  (96/8)
#define WFRAG_PER_LAYER (KS * NT * 32 * 2)   // 9216 uint32

// -------- scratch (static device globals; no allocation allowed) --------
__device__ __align__(16) float g_xw [N_NODES * D];   // X @ W (current layer)
__device__ __align__(16) float g_h  [N_NODES * D];   // layer-1 output
__device__ float g_dinv[N_NODES];                    // 1/sqrt(deg)
__device__ int   g_cnt [N_NODES];                    // in-degree histogram
__device__ int   g_rowptr[N_NODES + 1];              // CSR row pointers (by dst)
__device__ int   g_rowcur[N_NODES];                  // fill cursors
__device__ int   g_csr [N_EDGES];                    // CSR column indices (src)
__device__ __align__(16) unsigned g_wfrag[2 * WFRAG_PER_LAYER]; // tf32 W frags

__device__ __forceinline__ unsigned f2tf32(float f) {
    unsigned u;
    asm("cvt.rna.tf32.f32 %0, %1;" : "=r"(u) : "f"(f));
    return u;
}

// ---------------- CSR build ----------------
__global__ void k_count(const int* __restrict__ dst) {
    int e = blockIdx.x * blockDim.x + threadIdx.x;
    if (e < N_EDGES) atomicAdd(&g_cnt[dst[e]], 1);
}

// single-CTA exclusive prefix scan over 50k bins; writes rowptr/cursors/dinv
__global__ void __launch_bounds__(1024) k_scan() {
    __shared__ int wsum[32];
    const int T = 1024;
    const int CHUNK = (N_NODES + T - 1) / T;   // 49
    int t = threadIdx.x;
    int lane = t & 31, wid = t >> 5;
    int beg = t * CHUNK;
    int end = min(beg + CHUNK, N_NODES);
    if (beg > N_NODES) beg = N_NODES;
    if (end < beg) end = beg;

    int local = 0;
    for (int i = beg; i < end; i++) local += g_cnt[i];

    int v = local;
    #pragma unroll
    for (int off = 1; off < 32; off <<= 1) {
        int n = __shfl_up_sync(0xFFFFFFFFu, v, off);
        if (lane >= off) v += n;
    }
    if (lane == 31) wsum[wid] = v;
    __syncthreads();
    if (wid == 0) {
        int wv = wsum[lane];
        #pragma unroll
        for (int off = 1; off < 32; off <<= 1) {
            int n = __shfl_up_sync(0xFFFFFFFFu, wv, off);
            if (lane >= off) wv += n;
        }
        wsum[lane] = wv;
    }
    __syncthreads();

    int excl = v - local + (wid > 0 ? wsum[wid - 1] : 0);
    if (t == T - 1) g_rowptr[N_NODES] = excl + local;

    int acc = excl;
    for (int i = beg; i < end; i++) {
        g_rowptr[i] = acc;
        g_rowcur[i] = acc;
        int c = g_cnt[i];
        acc += c;
        g_dinv[i] = rsqrtf(1.0f + (float)c);
    }
}

__global__ void k_fill(const int* __restrict__ src,
                       const int* __restrict__ dst) {
    int e = blockIdx.x * blockDim.x + threadIdx.x;
    if (e >= N_EDGES) return;
    int d = dst[e];
    int pos = atomicAdd(&g_rowcur[d], 1);
    g_csr[pos] = src[e];
}

// ---------------- pack W1/W2 into per-lane tf32 B-fragments ----------------
// m16n8k8.tf32 B(col) fragment: b0 = W[k0+t][n0+g], b1 = W[k0+t+4][n0+g]
// with g = lane>>2, t = lane&3. Layout: [(ks*NT+nt)*32 + lane] * 2.
__global__ void k_wpack(const float* __restrict__ W1,
                        const float* __restrict__ W2) {
    int tid = blockIdx.x * blockDim.x + threadIdx.x;
    if (tid >= KS * NT * 32) return;
    int lane = tid & 31;
    int nt = (tid >> 5) % NT;
    int ks = (tid >> 5) / NT;
    int g = lane >> 2, t = lane & 3;
    int k0 = ks * 8, n0 = nt * 8;
    #pragma unroll
    for (int layer = 0; layer < 2; layer++) {
        const float* W = layer ? W2 : W1;
        unsigned b0 = f2tf32(W[(k0 + t) * D + n0 + g]);
        unsigned b1 = f2tf32(W[(k0 + t + 4) * D + n0 + g]);
        unsigned* dst = g_wfrag + layer * WFRAG_PER_LAYER + (size_t)tid * 2;
        dst[0] = b0;
        dst[1] = b1;
    }
}

// ---------------- tensor-core GEMM: g_xw = X @ W  (tf32 HMMA) ----------------
// 128 threads = 4 warps; warp owns 16 rows; 64 rows per CTA. No smem:
// A frags from global (X read once), B frags from L1-resident g_wfrag.
__global__ void __launch_bounds__(128)
k_gemm(const float* __restrict__ Xext, int use_h, int layer) {
    const float* __restrict__ X = use_h ? (const float*)g_h : Xext;
    int tid  = threadIdx.x;
    int warp = tid >> 5;
    int lane = tid & 31;
    int g = lane >> 2, t = lane & 3;

    int rowBase = blockIdx.x * 64 + warp * 16;
    int r_lo = rowBase + g;
    int r_hi = rowBase + g + 8;
    const float* __restrict__ plo = X + (size_t)min(r_lo, N_NODES - 1) * D;
    const float* __restrict__ phi = X + (size_t)min(r_hi, N_NODES - 1) * D;

    float c[NT][4];
    #pragma unroll
    for (int nt = 0; nt < NT; nt++)
        #pragma unroll
        for (int i = 0; i < 4; i++) c[nt][i] = 0.0f;

    const uint2* __restrict__ wf =
        reinterpret_cast<const uint2*>(g_wfrag + layer * WFRAG_PER_LAYER);

    #pragma unroll
    for (int ks = 0; ks < KS; ks++) {
        int k0 = ks * 8;
        unsigned a0 = f2tf32(plo[k0 + t]);
        unsigned a1 = f2tf32(phi[k0 + t]);
        unsigned a2 = f2tf32(plo[k0 + t + 4]);
        unsigned a3 = f2tf32(phi[k0 + t + 4]);
        const uint2* wrow = wf + (size_t)(ks * NT) * 32 + lane;
        #pragma unroll
        for (int nt = 0; nt < NT; nt++) {
            uint2 bb = wrow[nt * 32];
            asm("mma.sync.aligned.m16n8k8.row.col.f32.tf32.tf32.f32 "
                "{%0,%1,%2,%3}, {%4,%5,%6,%7}, {%8,%9}, {%0,%1,%2,%3};"
                : "+f"(c[nt][0]), "+f"(c[nt][1]), "+f"(c[nt][2]), "+f"(c[nt][3])
                : "r"(a0), "r"(a1), "r"(a2), "r"(a3), "r"(bb.x), "r"(bb.y));
        }
    }

    bool lo_ok = r_lo < N_NODES;
    bool hi_ok = r_hi < N_NODES;
    float2* __restrict__ out_lo = reinterpret_cast<float2*>(g_xw + (size_t)r_lo * D);
    float2* __restrict__ out_hi = reinterpret_cast<float2*>(g_xw + (size_t)r_hi * D);
    #pragma unroll
    for (int nt = 0; nt < NT; nt++) {
        int cp = (nt * 8 + 2 * t) >> 1;   // float2 index of col n0+2t
        if (lo_ok) out_lo[cp] = make_float2(c[nt][0], c[nt][1]);
        if (hi_ok) out_hi[cp] = make_float2(c[nt][2], c[nt][3]);
    }
}

// ---------------- fused aggregate + bias + relu (best-measured R4 form) ----
// One warp per node; lane handles columns {lane, lane+32, lane+64}.
__global__ void __launch_bounds__(256)
k_agg(const float* __restrict__ b, float* __restrict__ outExt, int to_h) {
    int warp = (blockIdx.x * blockDim.x + threadIdx.x) >> 5;
    int lane = threadIdx.x & 31;
    if (warp >= N_NODES) return;
    int i = warp;

    float di = g_dinv[i];
    const float* __restrict__ xwi = g_xw + (size_t)i * D;
    float a0 = xwi[lane]      * di;
    float a1 = xwi[lane + 32] * di;
    float a2 = xwi[lane + 64] * di;

    int beg = g_rowptr[i];
    int end = g_rowptr[i + 1];
    int j = beg;

    for (; j + 4 <= end; j += 4) {
        int s0 = g_csr[j + 0];
        int s1 = g_csr[j + 1];
        int s2 = g_csr[j + 2];
        int s3 = g_csr[j + 3];
        float w0 = g_dinv[s0], w1 = g_dinv[s1], w2 = g_dinv[s2], w3 = g_dinv[s3];
        const float* __restrict__ p0 = g_xw + (size_t)s0 * D;
        const float* __restrict__ p1 = g_xw + (size_t)s1 * D;
        const float* __restrict__ p2 = g_xw + (size_t)s2 * D;
        const float* __restrict__ p3 = g_xw + (size_t)s3 * D;
        float x00 = p0[lane], x01 = p0[lane + 32], x02 = p0[lane + 64];
        float x10 = p1[lane], x11 = p1[lane + 32], x12 = p1[lane + 64];
        float x20 = p2[lane], x21 = p2[lane + 32], x22 = p2[lane + 64];
        float x30 = p3[lane], x31 = p3[lane + 32], x32 = p3[lane + 64];
        a0 += x00 * w0; a1 += x01 * w0; a2 += x02 * w0;
        a0 += x10 * w1; a1 += x11 * w1; a2 += x12 * w1;
        a0 += x20 * w2; a1 += x21 * w2; a2 += x22 * w2;
        a0 += x30 * w3; a1 += x31 * w3; a2 += x32 * w3;
    }
    for (; j < end; j++) {
        int s = g_csr[j];
        float ws = g_dinv[s];
        const float* __restrict__ xs = g_xw + (size_t)s * D;
        a0 += xs[lane]      * ws;
        a1 += xs[lane + 32] * ws;
        a2 += xs[lane + 64] * ws;
    }

    float* __restrict__ out = to_h ? g_h : outExt;
    float* op = out + (size_t)i * D;
    op[lane]      = fmaxf(a0 * di + b[lane],      0.0f);
    op[lane + 32] = fmaxf(a1 * di + b[lane + 32], 0.0f);
    op[lane + 64] = fmaxf(a2 * di + b[lane + 64], 0.0f);
}

// ---------------- launch ----------------
extern "C" void kernel_launch(void* const* d_in, const int* in_sizes, int n_in,
                              void* d_out, int out_size) {
    const float* x   = (const float*)d_in[0];
    const int*   ei  = (const int*)d_in[1];   // [2, E] int32 (JAX x64 disabled)
    const float* W1  = (const float*)d_in[2];
    const float* b1  = (const float*)d_in[3];
    const float* W2  = (const float*)d_in[4];
    const float* b2  = (const float*)d_in[5];
    float*       out = (float*)d_out;

    const int* src = ei;
    const int* dst = ei + N_EDGES;

    // zero the histogram via memset node (no kernel launch)
    void* cntPtr = nullptr;
    cudaGetSymbolAddress(&cntPtr, g_cnt);
    cudaMemsetAsync(cntPtr, 0, N_NODES * sizeof(int));

    const int T = 256;
    int gE    = (N_EDGES + T - 1) / T;
    int gGemm = (N_NODES + 63) / 64;          // 64 rows per 128-thr CTA
    int gAgg  = (N_NODES * 32 + T - 1) / T;   // warp per node
    int gPack = (KS * NT * 32 + T - 1) / T;

    // CSR build + norms + W fragment pack (shared by both layers)
    k_count <<<gE, T>>>(dst);
    k_wpack <<<gPack, T>>>(W1, W2);
    k_scan  <<<1, 1024>>>();
    k_fill  <<<gE, T>>>(src, dst);

    // layer 1: h = relu(agg(x @ W1) + b1)
    k_gemm <<<gGemm, 128>>>(x, 0, 0);
    k_agg  <<<gAgg, T>>>(b1, out, 1);

    // layer 2: out = relu(agg(h @ W2) + b2)
    k_gemm <<<gGemm, 128>>>(nullptr, 1, 1);
    k_agg  <<<gAgg, T>>>(b2, out, 0);
}

// round 9
// speedup vs baseline: 1.3191x; 1.0260x over previous
#include <cuda_runtime.h>
#include <cuda_bf16.h>
#include <cstdint>

#define N_NODES 50000
#define N_EDGES 800000
#define D 96
#define KS 12              // k-steps  (96/8)
#define NT 12              // n-tiles  (96/8)
#define WFRAG_PER_LAYER (KS * NT * 32 * 2)   // 9216 uint32
#define G_COUNT 3125       // blocks for count part (800000/256)
#define G_WPACK 18         // blocks for wpack part (4608/256)
#define G_GEMM  391        // blocks for gemm (128 rows per 256-thr CTA)
#define G_FILL  3125

// -------- scratch (static device globals; no allocation allowed) --------
__device__ __align__(16) float g_xw [N_NODES * D];   // X @ W (current layer)
__device__ __align__(16) float g_h  [N_NODES * D];   // layer-1 output
__device__ float g_dinv[N_NODES];                    // 1/sqrt(deg)
__device__ int   g_cnt [N_NODES];                    // in-degree histogram
__device__ int   g_rowptr[N_NODES + 1];              // CSR row pointers (by dst)
__device__ int   g_rowcur[N_NODES];                  // fill cursors
__device__ int   g_csr [N_EDGES];                    // CSR column indices (src)
__device__ __align__(16) unsigned g_wfrag[2 * WFRAG_PER_LAYER]; // tf32 W frags

__device__ __forceinline__ unsigned f2tf32(float f) {
    unsigned u;
    asm("cvt.rna.tf32.f32 %0, %1;" : "=r"(u) : "f"(f));
    return u;
}

// ---------------- warp-level tf32 GEMM tile: 16 rows x 96 cols ----------------
__device__ __forceinline__ void gemm_warp_tile(
    const float* __restrict__ X, int layer, int rowBase, int lane) {
    int g = lane >> 2, t = lane & 3;
    int r_lo = rowBase + g;
    int r_hi = rowBase + g + 8;
    const float* __restrict__ plo = X + (size_t)min(r_lo, N_NODES - 1) * D;
    const float* __restrict__ phi = X + (size_t)min(r_hi, N_NODES - 1) * D;

    float c[NT][4];
    #pragma unroll
    for (int nt = 0; nt < NT; nt++)
        #pragma unroll
        for (int i = 0; i < 4; i++) c[nt][i] = 0.0f;

    const uint2* __restrict__ wf =
        reinterpret_cast<const uint2*>(g_wfrag + layer * WFRAG_PER_LAYER);

    #pragma unroll
    for (int ks = 0; ks < KS; ks++) {
        int k0 = ks * 8;
        unsigned a0 = f2tf32(plo[k0 + t]);
        unsigned a1 = f2tf32(phi[k0 + t]);
        unsigned a2 = f2tf32(plo[k0 + t + 4]);
        unsigned a3 = f2tf32(phi[k0 + t + 4]);
        const uint2* wrow = wf + (size_t)(ks * NT) * 32 + lane;
        #pragma unroll
        for (int nt = 0; nt < NT; nt++) {
            uint2 bb = wrow[nt * 32];
            asm("mma.sync.aligned.m16n8k8.row.col.f32.tf32.tf32.f32 "
                "{%0,%1,%2,%3}, {%4,%5,%6,%7}, {%8,%9}, {%0,%1,%2,%3};"
                : "+f"(c[nt][0]), "+f"(c[nt][1]), "+f"(c[nt][2]), "+f"(c[nt][3])
                : "r"(a0), "r"(a1), "r"(a2), "r"(a3), "r"(bb.x), "r"(bb.y));
        }
    }

    bool lo_ok = r_lo < N_NODES;
    bool hi_ok = r_hi < N_NODES;
    float2* __restrict__ out_lo = reinterpret_cast<float2*>(g_xw + (size_t)r_lo * D);
    float2* __restrict__ out_hi = reinterpret_cast<float2*>(g_xw + (size_t)r_hi * D);
    #pragma unroll
    for (int nt = 0; nt < NT; nt++) {
        int cp = (nt * 8 + 2 * t) >> 1;
        if (lo_ok) out_lo[cp] = make_float2(c[nt][0], c[nt][1]);
        if (hi_ok) out_hi[cp] = make_float2(c[nt][2], c[nt][3]);
    }
}

// ---------------- fused: edge count histogram + W fragment pack ----------------
__global__ void __launch_bounds__(256)
k_prep(const int* __restrict__ dst,
       const float* __restrict__ W1, const float* __restrict__ W2) {
    if (blockIdx.x < G_COUNT) {
        int e = blockIdx.x * 256 + threadIdx.x;
        if (e < N_EDGES) atomicAdd(&g_cnt[dst[e]], 1);
    } else {
        int tid = (blockIdx.x - G_COUNT) * 256 + threadIdx.x;
        if (tid >= KS * NT * 32) return;
        int lane = tid & 31;
        int nt = (tid >> 5) % NT;
        int ks = (tid >> 5) / NT;
        int g = lane >> 2, t = lane & 3;
        int k0 = ks * 8, n0 = nt * 8;
        #pragma unroll
        for (int layer = 0; layer < 2; layer++) {
            const float* W = layer ? W2 : W1;
            unsigned b0 = f2tf32(W[(k0 + t) * D + n0 + g]);
            unsigned b1 = f2tf32(W[(k0 + t + 4) * D + n0 + g]);
            unsigned* dp = g_wfrag + layer * WFRAG_PER_LAYER + (size_t)tid * 2;
            dp[0] = b0;
            dp[1] = b1;
        }
    }
}

// single-CTA exclusive prefix scan over 50k bins; writes rowptr/cursors/dinv
__global__ void __launch_bounds__(1024) k_scan() {
    __shared__ int wsum[32];
    const int T = 1024;
    const int CHUNK = (N_NODES + T - 1) / T;   // 49
    int t = threadIdx.x;
    int lane = t & 31, wid = t >> 5;
    int beg = t * CHUNK;
    int end = min(beg + CHUNK, N_NODES);
    if (beg > N_NODES) beg = N_NODES;
    if (end < beg) end = beg;

    int local = 0;
    for (int i = beg; i < end; i++) local += g_cnt[i];

    int v = local;
    #pragma unroll
    for (int off = 1; off < 32; off <<= 1) {
        int n = __shfl_up_sync(0xFFFFFFFFu, v, off);
        if (lane >= off) v += n;
    }
    if (lane == 31) wsum[wid] = v;
    __syncthreads();
    if (wid == 0) {
        int wv = wsum[lane];
        #pragma unroll
        for (int off = 1; off < 32; off <<= 1) {
            int n = __shfl_up_sync(0xFFFFFFFFu, wv, off);
            if (lane >= off) wv += n;
        }
        wsum[lane] = wv;
    }
    __syncthreads();

    int excl = v - local + (wid > 0 ? wsum[wid - 1] : 0);
    if (t == T - 1) g_rowptr[N_NODES] = excl + local;

    int acc = excl;
    for (int i = beg; i < end; i++) {
        g_rowptr[i] = acc;
        g_rowcur[i] = acc;
        int c = g_cnt[i];
        acc += c;
        g_dinv[i] = rsqrtf(1.0f + (float)c);
    }
}

// ---------------- fused: CSR fill + layer-1 GEMM (independent work) ----------
__global__ void __launch_bounds__(256)
k_fill_gemm(const int* __restrict__ src, const int* __restrict__ dst,
            const float* __restrict__ x) {
    if (blockIdx.x < G_GEMM) {
        int warp = threadIdx.x >> 5;
        int lane = threadIdx.x & 31;
        int rowBase = blockIdx.x * 128 + warp * 16;
        gemm_warp_tile(x, 0, rowBase, lane);
    } else {
        int e = (blockIdx.x - G_GEMM) * 256 + threadIdx.x;
        if (e >= N_EDGES) return;
        int d = dst[e];
        int pos = atomicAdd(&g_rowcur[d], 1);
        g_csr[pos] = src[e];
    }
}

// ---------------- layer-2 GEMM ----------------
__global__ void __launch_bounds__(256)
k_gemm2() {
    int warp = threadIdx.x >> 5;
    int lane = threadIdx.x & 31;
    int rowBase = blockIdx.x * 128 + warp * 16;
    gemm_warp_tile((const float*)g_h, 1, rowBase, lane);
}

// ---------------- fused aggregate + bias + relu (best-measured form) --------
// One warp per node; lane handles columns {lane, lane+32, lane+64}.
__global__ void __launch_bounds__(256)
k_agg(const float* __restrict__ b, float* __restrict__ outExt, int to_h) {
    int warp = (blockIdx.x * blockDim.x + threadIdx.x) >> 5;
    int lane = threadIdx.x & 31;
    if (warp >= N_NODES) return;
    int i = warp;

    float di = g_dinv[i];
    const float* __restrict__ xwi = g_xw + (size_t)i * D;
    float a0 = xwi[lane]      * di;
    float a1 = xwi[lane + 32] * di;
    float a2 = xwi[lane + 64] * di;

    int beg = g_rowptr[i];
    int end = g_rowptr[i + 1];
    int j = beg;

    for (; j + 4 <= end; j += 4) {
        int s0 = g_csr[j + 0];
        int s1 = g_csr[j + 1];
        int s2 = g_csr[j + 2];
        int s3 = g_csr[j + 3];
        float w0 = g_dinv[s0], w1 = g_dinv[s1], w2 = g_dinv[s2], w3 = g_dinv[s3];
        const float* __restrict__ p0 = g_xw + (size_t)s0 * D;
        const float* __restrict__ p1 = g_xw + (size_t)s1 * D;
        const float* __restrict__ p2 = g_xw + (size_t)s2 * D;
        const float* __restrict__ p3 = g_xw + (size_t)s3 * D;
        float x00 = p0[lane], x01 = p0[lane + 32], x02 = p0[lane + 64];
        float x10 = p1[lane], x11 = p1[lane + 32], x12 = p1[lane + 64];
        float x20 = p2[lane], x21 = p2[lane + 32], x22 = p2[lane + 64];
        float x30 = p3[lane], x31 = p3[lane + 32], x32 = p3[lane + 64];
        a0 += x00 * w0; a1 += x01 * w0; a2 += x02 * w0;
        a0 += x10 * w1; a1 += x11 * w1; a2 += x12 * w1;
        a0 += x20 * w2; a1 += x21 * w2; a2 += x22 * w2;
        a0 += x30 * w3; a1 += x31 * w3; a2 += x32 * w3;
    }
    for (; j < end; j++) {
        int s = g_csr[j];
        float ws = g_dinv[s];
        const float* __restrict__ xs = g_xw + (size_t)s * D;
        a0 += xs[lane]      * ws;
        a1 += xs[lane + 32] * ws;
        a2 += xs[lane + 64] * ws;
    }

    float* __restrict__ out = to_h ? g_h : outExt;
    float* op = out + (size_t)i * D;
    op[lane]      = fmaxf(a0 * di + b[lane],      0.0f);
    op[lane + 32] = fmaxf(a1 * di + b[lane + 32], 0.0f);
    op[lane + 64] = fmaxf(a2 * di + b[lane + 64], 0.0f);
}

// ---------------- launch ----------------
extern "C" void kernel_launch(void* const* d_in, const int* in_sizes, int n_in,
                              void* d_out, int out_size) {
    const float* x   = (const float*)d_in[0];
    const int*   ei  = (const int*)d_in[1];   // [2, E] int32 (JAX x64 disabled)
    const float* W1  = (const float*)d_in[2];
    const float* b1  = (const float*)d_in[3];
    const float* W2  = (const float*)d_in[4];
    const float* b2  = (const float*)d_in[5];
    float*       out = (float*)d_out;

    const int* src = ei;
    const int* dst = ei + N_EDGES;

    // zero the histogram via memset node (launch 1)
    void* cntPtr = nullptr;
    cudaGetSymbolAddress(&cntPtr, g_cnt);
    cudaMemsetAsync(cntPtr, 0, N_NODES * sizeof(int));

    const int T = 256;
    int gAgg = (N_NODES * 32 + T - 1) / T;   // warp per node

    // (2) count + wpack fused
    k_prep <<<G_COUNT + G_WPACK, T>>>(dst, W1, W2);
    // (3) scan
    k_scan <<<1, 1024>>>();
    // (4) CSR fill + layer-1 GEMM fused (independent pipes overlap)
    k_fill_gemm <<<G_GEMM + G_FILL, T>>>(src, dst, x);
    // (5) layer-1 aggregate  <- ncu capture slot
    k_agg <<<gAgg, T>>>(b1, out, 1);
    // (6) layer-2 GEMM
    k_gemm2 <<<G_GEMM, T>>>();
    // (7) layer-2 aggregate
    k_agg <<<gAgg, T>>>(b2, out, 0);
}

// round 10
// speedup vs baseline: 1.3253x; 1.0047x over previous
#include <cuda_runtime.h>
#include <cuda_bf16.h>
#include <cstdint>

#define N_NODES 50000
#define N_EDGES 800000
#define D 96
#define ROWB (D * 4)       // row stride in bytes (384)
#define KS 12              // k-steps  (96/8)
#define NT 12              // n-tiles  (96/8)
#define WFRAG_PER_LAYER (KS * NT * 32 * 2)   // 9216 uint32
#define G_COUNT 3125       // blocks for count part (800000/256)
#define G_WPACK 18         // blocks for wpack part (4608/256)
#define G_GEMM  391        // blocks for gemm (128 rows per 256-thr CTA)
#define G_FILL  3125

// -------- scratch (static device globals; no allocation allowed) --------
__device__ __align__(16) float g_xw [N_NODES * D];   // (X @ W) * dinv  (pre-scaled)
__device__ __align__(16) float g_h  [N_NODES * D];   // layer-1 output
__device__ float g_dinv[N_NODES];                    // 1/sqrt(deg)
__device__ int   g_cnt [N_NODES];                    // in-degree histogram
__device__ int   g_rowptr[N_NODES + 1];              // CSR row pointers (by dst)
__device__ int   g_rowcur[N_NODES];                  // fill cursors
__device__ int   g_csr [N_EDGES];                    // CSR: src row BYTE offsets
__device__ __align__(16) unsigned g_wfrag[2 * WFRAG_PER_LAYER]; // tf32 W frags

__device__ __forceinline__ unsigned f2tf32(float f) {
    unsigned u;
    asm("cvt.rna.tf32.f32 %0, %1;" : "=r"(u) : "f"(f));
    return u;
}

// ---------------- warp-level tf32 GEMM tile: 16 rows x 96 cols --------------
// Epilogue pre-scales each output row by dinv[row].
__device__ __forceinline__ void gemm_warp_tile(
    const float* __restrict__ X, int layer, int rowBase, int lane) {
    int g = lane >> 2, t = lane & 3;
    int r_lo = rowBase + g;
    int r_hi = rowBase + g + 8;
    int c_lo = min(r_lo, N_NODES - 1);
    int c_hi = min(r_hi, N_NODES - 1);
    const float* __restrict__ plo = X + (size_t)c_lo * D;
    const float* __restrict__ phi = X + (size_t)c_hi * D;

    float c[NT][4];
    #pragma unroll
    for (int nt = 0; nt < NT; nt++)
        #pragma unroll
        for (int i = 0; i < 4; i++) c[nt][i] = 0.0f;

    const uint2* __restrict__ wf =
        reinterpret_cast<const uint2*>(g_wfrag + layer * WFRAG_PER_LAYER);

    #pragma unroll
    for (int ks = 0; ks < KS; ks++) {
        int k0 = ks * 8;
        unsigned a0 = f2tf32(plo[k0 + t]);
        unsigned a1 = f2tf32(phi[k0 + t]);
        unsigned a2 = f2tf32(plo[k0 + t + 4]);
        unsigned a3 = f2tf32(phi[k0 + t + 4]);
        const uint2* wrow = wf + (size_t)(ks * NT) * 32 + lane;
        #pragma unroll
        for (int nt = 0; nt < NT; nt++) {
            uint2 bb = wrow[nt * 32];
            asm("mma.sync.aligned.m16n8k8.row.col.f32.tf32.tf32.f32 "
                "{%0,%1,%2,%3}, {%4,%5,%6,%7}, {%8,%9}, {%0,%1,%2,%3};"
                : "+f"(c[nt][0]), "+f"(c[nt][1]), "+f"(c[nt][2]), "+f"(c[nt][3])
                : "r"(a0), "r"(a1), "r"(a2), "r"(a3), "r"(bb.x), "r"(bb.y));
        }
    }

    float dlo = g_dinv[c_lo];
    float dhi = g_dinv[c_hi];
    bool lo_ok = r_lo < N_NODES;
    bool hi_ok = r_hi < N_NODES;
    float2* __restrict__ out_lo = reinterpret_cast<float2*>(g_xw + (size_t)r_lo * D);
    float2* __restrict__ out_hi = reinterpret_cast<float2*>(g_xw + (size_t)r_hi * D);
    #pragma unroll
    for (int nt = 0; nt < NT; nt++) {
        int cp = (nt * 8 + 2 * t) >> 1;
        if (lo_ok) out_lo[cp] = make_float2(c[nt][0] * dlo, c[nt][1] * dlo);
        if (hi_ok) out_hi[cp] = make_float2(c[nt][2] * dhi, c[nt][3] * dhi);
    }
}

// ---------------- fused: edge count histogram + W fragment pack -------------
__global__ void __launch_bounds__(256)
k_prep(const int* __restrict__ dst,
       const float* __restrict__ W1, const float* __restrict__ W2) {
    if (blockIdx.x < G_COUNT) {
        int e = blockIdx.x * 256 + threadIdx.x;
        if (e < N_EDGES) atomicAdd(&g_cnt[dst[e]], 1);
    } else {
        int tid = (blockIdx.x - G_COUNT) * 256 + threadIdx.x;
        if (tid >= KS * NT * 32) return;
        int lane = tid & 31;
        int nt = (tid >> 5) % NT;
        int ks = (tid >> 5) / NT;
        int g = lane >> 2, t = lane & 3;
        int k0 = ks * 8, n0 = nt * 8;
        #pragma unroll
        for (int layer = 0; layer < 2; layer++) {
            const float* W = layer ? W2 : W1;
            unsigned b0 = f2tf32(W[(k0 + t) * D + n0 + g]);
            unsigned b1 = f2tf32(W[(k0 + t + 4) * D + n0 + g]);
            unsigned* dp = g_wfrag + layer * WFRAG_PER_LAYER + (size_t)tid * 2;
            dp[0] = b0;
            dp[1] = b1;
        }
    }
}

// single-CTA exclusive prefix scan over 50k bins; writes rowptr/cursors/dinv
__global__ void __launch_bounds__(1024) k_scan() {
    __shared__ int wsum[32];
    const int T = 1024;
    const int CHUNK = (N_NODES + T - 1) / T;   // 49
    int t = threadIdx.x;
    int lane = t & 31, wid = t >> 5;
    int beg = t * CHUNK;
    int end = min(beg + CHUNK, N_NODES);
    if (beg > N_NODES) beg = N_NODES;
    if (end < beg) end = beg;

    int local = 0;
    for (int i = beg; i < end; i++) local += g_cnt[i];

    int v = local;
    #pragma unroll
    for (int off = 1; off < 32; off <<= 1) {
        int n = __shfl_up_sync(0xFFFFFFFFu, v, off);
        if (lane >= off) v += n;
    }
    if (lane == 31) wsum[wid] = v;
    __syncthreads();
    if (wid == 0) {
        int wv = wsum[lane];
        #pragma unroll
        for (int off = 1; off < 32; off <<= 1) {
            int n = __shfl_up_sync(0xFFFFFFFFu, wv, off);
            if (lane >= off) wv += n;
        }
        wsum[lane] = wv;
    }
    __syncthreads();

    int excl = v - local + (wid > 0 ? wsum[wid - 1] : 0);
    if (t == T - 1) g_rowptr[N_NODES] = excl + local;

    int acc = excl;
    for (int i = beg; i < end; i++) {
        g_rowptr[i] = acc;
        g_rowcur[i] = acc;
        int c = g_cnt[i];
        acc += c;
        g_dinv[i] = rsqrtf(1.0f + (float)c);
    }
}

// ---------------- fused: CSR fill (byte offsets) + layer-1 GEMM -------------
__global__ void __launch_bounds__(256)
k_fill_gemm(const int* __restrict__ src, const int* __restrict__ dst,
            const float* __restrict__ x) {
    if (blockIdx.x < G_GEMM) {
        int warp = threadIdx.x >> 5;
        int lane = threadIdx.x & 31;
        int rowBase = blockIdx.x * 128 + warp * 16;
        gemm_warp_tile(x, 0, rowBase, lane);
    } else {
        int e = (blockIdx.x - G_GEMM) * 256 + threadIdx.x;
        if (e >= N_EDGES) return;
        int d = dst[e];
        int pos = atomicAdd(&g_rowcur[d], 1);
        g_csr[pos] = src[e] * ROWB;       // store BYTE offset of source row
    }
}

// ---------------- layer-2 GEMM ----------------
__global__ void __launch_bounds__(256)
k_gemm2() {
    int warp = threadIdx.x >> 5;
    int lane = threadIdx.x & 31;
    int rowBase = blockIdx.x * 128 + warp * 16;
    gemm_warp_tile((const float*)g_h, 1, rowBase, lane);
}

// ---------------- fused aggregate + bias + relu -----------------------------
// Rows in g_xw are pre-scaled by dinv[src]; csr holds byte offsets.
// Per edge: 1 uniform LDG (offset) + 3 row LDG + 3 FADD.
__global__ void __launch_bounds__(256)
k_agg(const float* __restrict__ b, float* __restrict__ outExt, int to_h) {
    int warp = (blockIdx.x * blockDim.x + threadIdx.x) >> 5;
    int lane = threadIdx.x & 31;
    if (warp >= N_NODES) return;
    int i = warp;

    float di = g_dinv[i];
    const char* __restrict__ basep = (const char*)g_xw;
    const float* __restrict__ xwi = g_xw + (size_t)i * D;   // pre-scaled self
    float a0 = xwi[lane];
    float a1 = xwi[lane + 32];
    float a2 = xwi[lane + 64];

    int beg = g_rowptr[i];
    int end = g_rowptr[i + 1];
    int j = beg;

    for (; j + 4 <= end; j += 4) {
        int o0 = g_csr[j + 0];
        int o1 = g_csr[j + 1];
        int o2 = g_csr[j + 2];
        int o3 = g_csr[j + 3];
        const float* __restrict__ p0 = (const float*)(basep + o0);
        const float* __restrict__ p1 = (const float*)(basep + o1);
        const float* __restrict__ p2 = (const float*)(basep + o2);
        const float* __restrict__ p3 = (const float*)(basep + o3);
        float x00 = p0[lane], x01 = p0[lane + 32], x02 = p0[lane + 64];
        float x10 = p1[lane], x11 = p1[lane + 32], x12 = p1[lane + 64];
        float x20 = p2[lane], x21 = p2[lane + 32], x22 = p2[lane + 64];
        float x30 = p3[lane], x31 = p3[lane + 32], x32 = p3[lane + 64];
        a0 += x00; a1 += x01; a2 += x02;
        a0 += x10; a1 += x11; a2 += x12;
        a0 += x20; a1 += x21; a2 += x22;
        a0 += x30; a1 += x31; a2 += x32;
    }
    for (; j < end; j++) {
        int o = g_csr[j];
        const float* __restrict__ p = (const float*)(basep + o);
        a0 += p[lane];
        a1 += p[lane + 32];
        a2 += p[lane + 64];
    }

    float* __restrict__ out = to_h ? g_h : outExt;
    float* op = out + (size_t)i * D;
    op[lane]      = fmaxf(a0 * di + b[lane],      0.0f);
    op[lane + 32] = fmaxf(a1 * di + b[lane + 32], 0.0f);
    op[lane + 64] = fmaxf(a2 * di + b[lane + 64], 0.0f);
}

// ---------------- launch ----------------
extern "C" void kernel_launch(void* const* d_in, const int* in_sizes, int n_in,
                              void* d_out, int out_size) {
    const float* x   = (const float*)d_in[0];
    const int*   ei  = (const int*)d_in[1];   // [2, E] int32 (JAX x64 disabled)
    const float* W1  = (const float*)d_in[2];
    const float* b1  = (const float*)d_in[3];
    const float* W2  = (const float*)d_in[4];
    const float* b2  = (const float*)d_in[5];
    float*       out = (float*)d_out;

    const int* src = ei;
    const int* dst = ei + N_EDGES;

    // zero the histogram via memset node (launch 1)
    void* cntPtr = nullptr;
    cudaGetSymbolAddress(&cntPtr, g_cnt);
    cudaMemsetAsync(cntPtr, 0, N_NODES * sizeof(int));

    const int T = 256;
    int gAgg = (N_NODES * 32 + T - 1) / T;   // warp per node

    // (2) count + wpack fused
    k_prep <<<G_COUNT + G_WPACK, T>>>(dst, W1, W2);
    // (3) scan (rowptr, cursors, dinv)
    k_scan <<<1, 1024>>>();
    // (4) CSR fill + layer-1 GEMM fused
    k_fill_gemm <<<G_GEMM + G_FILL, T>>>(src, dst, x);
    // (5) layer-1 aggregate  <- ncu capture slot
    k_agg <<<gAgg, T>>>(b1, out, 1);
    // (6) layer-2 GEMM
    k_gemm2 <<<G_GEMM, T>>>();
    // (7) layer-2 aggregate
    k_agg <<<gAgg, T>>>(b2, out, 0);
}